// round 3
// baseline (speedup 1.0000x reference)
#include <cuda_runtime.h>

#define EPSBN 1e-5f
#define ALPHA 0.2f

static constexpr int B = 16, N = 4096, P = 1024, S = 32;
static constexpr int NTILES = (B * P) / 4;   // 4096 tiles, 4 groups each
static constexpr int OUT2_OFF = B * 3 * P;   // 49152

// fused transposed features: [b][n][0..2]=xyz, [3..66]=points, [67]=0
__device__ __align__(16) float g_xpt[(size_t)B * N * 68];

// ---------------------------------------------------------------------------
// Kernel 1: transpose (B,3,N)+(B,64,N) channel-major -> (B,N,68) row-major
// ---------------------------------------------------------------------------
__global__ void __launch_bounds__(256) transpose_kernel(
    const float* __restrict__ xyz, const float* __restrict__ pts)
{
    __shared__ float sm[67 * 65];
    int b  = blockIdx.x >> 6;
    int n0 = (blockIdx.x & 63) << 6;
    int t  = threadIdx.x;
    for (int idx = t; idx < 67 * 64; idx += 256) {
        int c = idx >> 6, i = idx & 63;
        float v = (c < 3) ? xyz[(b * 3 + c) * N + n0 + i]
                          : pts[(b * 64 + (c - 3)) * N + n0 + i];
        sm[c * 65 + i] = v;
    }
    __syncthreads();
    for (int idx = t; idx < 64 * 17; idx += 256) {
        int row = idx / 17, c4 = idx % 17;
        int cb = c4 << 2;
        float4 v;
        v.x = sm[(cb + 0) * 65 + row];
        v.y = sm[(cb + 1) * 65 + row];
        v.z = sm[(cb + 2) * 65 + row];
        v.w = (cb + 3 < 67) ? sm[(cb + 3) * 65 + row] : 0.f;
        *(float4*)&g_xpt[((size_t)(b * N + n0 + row)) * 68 + cb] = v;
    }
}

// ---------------------------------------------------------------------------
// Shared-memory GEMM: out[r][d] = relu(sum_k in[r][k]*W[d][k] + bias[d])
// in: 132 rows, stride 68.  W: rows are output channels, stride 68.
// Thread tiling: 4 rows x 8 cols per thread (cols strided by 8 -> bank-clean).
// ---------------------------------------------------------------------------
__device__ __forceinline__ void gemm_relu(
    const float* __restrict__ sIn, const float* __restrict__ sW,
    const float* __restrict__ sBias, float* __restrict__ sOut,
    int outStride, int K4, int dOff, int t)
{
    int d_blk = t & 7;
    int rb0   = t >> 3;
    for (int rb = rb0; rb < 33; rb += 32) {
        int r0 = rb << 2;
        float acc[4][8];
#pragma unroll
        for (int i = 0; i < 4; i++)
#pragma unroll
            for (int j = 0; j < 8; j++) acc[i][j] = 0.f;
        for (int k4 = 0; k4 < K4; k4++) {
            float4 xv[4];
#pragma unroll
            for (int i = 0; i < 4; i++)
                xv[i] = *(const float4*)&sIn[(r0 + i) * 68 + (k4 << 2)];
#pragma unroll
            for (int j = 0; j < 8; j++) {
                float4 wv = *(const float4*)&sW[(dOff + d_blk + (j << 3)) * 68 + (k4 << 2)];
#pragma unroll
                for (int i = 0; i < 4; i++) {
                    acc[i][j] += xv[i].x * wv.x;
                    acc[i][j] += xv[i].y * wv.y;
                    acc[i][j] += xv[i].z * wv.z;
                    acc[i][j] += xv[i].w * wv.w;
                }
            }
        }
#pragma unroll
        for (int j = 0; j < 8; j++) {
            int d = dOff + d_blk + (j << 3);
            float bb = sBias[d];
#pragma unroll
            for (int i = 0; i < 4; i++) {
                float v = acc[i][j] + bb;
                sOut[(r0 + i) * outStride + d] = v > 0.f ? v : 0.f;
            }
        }
    }
}

// ---------------------------------------------------------------------------
// Main fused kernel: persistent CTAs, each tile = 4 groups (132 rows)
// smem layout (floats):
//  W1s 0(4352) W2s 4352(4352) W3s 8704(8704) c1 17408(64) c2 17472(64)
//  c3 17536(128) X 17664(8976) H1 26640(8976) H3 35616(17424)
//  Fp 53040(512) relx 53552(384) nX 53936(16) rowGi 53952(132) -> 54084 fl
// 'a' (131x128 = 16768 fl) overlays X+H1 during the attention phase.
// ---------------------------------------------------------------------------
__global__ void __launch_bounds__(256, 1) main_kernel(
    const int* __restrict__ fpsIdx, const int* __restrict__ grpIdx,
    const float* __restrict__ w1, const float* __restrict__ b1,
    const float* __restrict__ g1, const float* __restrict__ bt1,
    const float* __restrict__ m1, const float* __restrict__ v1,
    const float* __restrict__ w2, const float* __restrict__ b2,
    const float* __restrict__ g2, const float* __restrict__ bt2,
    const float* __restrict__ m2, const float* __restrict__ v2,
    const float* __restrict__ w3, const float* __restrict__ b3,
    const float* __restrict__ g3, const float* __restrict__ bt3,
    const float* __restrict__ m3, const float* __restrict__ v3,
    const float* __restrict__ aG,
    float* __restrict__ out)
{
    extern __shared__ float sm[];
    float* W1s  = sm;
    float* W2s  = sm + 4352;
    float* W3s  = sm + 8704;
    float* c1s  = sm + 17408;
    float* c2s  = sm + 17472;
    float* c3s  = sm + 17536;
    float* X    = sm + 17664;   // also aSm during attention
    float* H1   = sm + 26640;
    float* H3   = sm + 35616;
    float* Fp   = sm + 53040;
    float* relx = sm + 53552;
    float* nX   = sm + 53936;
    int*  rowGi = (int*)(sm + 53952);
    float* aSm  = X;

    int t = threadIdx.x;

    // fold BN into weights (once per CTA)
    for (int idx = t; idx < 64 * 68; idx += 256) {
        int d = idx / 68, k = idx % 68;
        float s1 = g1[d] * rsqrtf(v1[d] + EPSBN);
        float s2 = g2[d] * rsqrtf(v2[d] + EPSBN);
        W1s[idx] = (k < 67) ? w1[d * 67 + k] * s1 : 0.f;
        W2s[idx] = (k < 64) ? w2[d * 64 + k] * s2 : 0.f;
    }
    for (int idx = t; idx < 128 * 68; idx += 256) {
        int d = idx / 68, k = idx % 68;
        float s3 = g3[d] * rsqrtf(v3[d] + EPSBN);
        W3s[idx] = (k < 64) ? w3[d * 64 + k] * s3 : 0.f;
    }
    if (t < 64) {
        float s1 = g1[t] * rsqrtf(v1[t] + EPSBN);
        float s2 = g2[t] * rsqrtf(v2[t] + EPSBN);
        c1s[t] = (b1[t] - m1[t]) * s1 + bt1[t];
        c2s[t] = (b2[t] - m2[t]) * s2 + bt2[t];
    }
    if (t < 128) {
        float s3 = g3[t] * rsqrtf(v3[t] + EPSBN);
        c3s[t] = (b3[t] - m3[t]) * s3 + bt3[t];
    }

    for (int tile = blockIdx.x; tile < NTILES; tile += gridDim.x) {
        __syncthreads();                       // protect smem from prev tile
        int b  = tile >> 8;
        int p0 = (tile & 255) << 2;

        if (t < 132) {
            int gi;
            if (t < 128) gi = grpIdx[((b * P + p0 + (t >> 5)) << 5) + (t & 31)];
            else         gi = fpsIdx[b * P + p0 + (t - 128)];
            rowGi[t] = gi;
        }
        __syncthreads();
        if (t < 12) {
            int p = t / 3, c = t % 3;
            float v = g_xpt[((size_t)(b * N + rowGi[128 + p])) * 68 + c];
            nX[p * 4 + c] = v;
            out[(b * 3 + c) * P + p0 + p] = v;   // new_xyz output (B,3,P)
        }
        __syncthreads();

        // gather 132 feature rows (67 valid floats each)
        for (int idx = t; idx < 132 * 17; idx += 256) {
            int row = idx / 17, c4 = idx % 17;
            float4 v = *(const float4*)&g_xpt[((size_t)(b * N + rowGi[row])) * 68 + (c4 << 2)];
            if (c4 == 0 && row < 128) {          // relative xyz for neighbor rows
                int p = row >> 5;
                v.x -= nX[p * 4 + 0];
                v.y -= nX[p * 4 + 1];
                v.z -= nX[p * 4 + 2];
                relx[row * 3 + 0] = v.x;
                relx[row * 3 + 1] = v.y;
                relx[row * 3 + 2] = v.z;
            }
            *(float4*)&X[row * 68 + (c4 << 2)] = v;
        }
        __syncthreads();

        gemm_relu(X,  W1s, c1s, H1, 68,  17, 0,  t);   // 67 -> 64
        __syncthreads();
        gemm_relu(H1, W2s, c2s, X,  68,  16, 0,  t);   // 64 -> 64 (H2 in X)
        __syncthreads();
        gemm_relu(X,  W3s, c3s, H3, 132, 16, 0,  t);   // 64 -> 128
        gemm_relu(X,  W3s, c3s, H3, 132, 16, 64, t);
        __syncthreads();

        // load attention matrix a into freed X+H1 region
        for (int idx = t; idx < (131 * 128) / 4; idx += 256)
            *(float4*)&aSm[idx << 2] = *(const float4*)&aG[idx << 2];
        __syncthreads();

        // Fp[p][d] = fps_h3[p] . a[3:,d]
        for (int idx = t; idx < 512; idx += 256) {
            int pl = idx >> 7, d = idx & 127;
            const float* hrow = &H3[(128 + pl) * 132];
            float s = 0.f;
            for (int k = 0; k < 128; k++)
                s += hrow[k] * aSm[(3 + k) * 128 + d];
            Fp[idx] = s;
        }
        __syncthreads();

        // attention: thread owns one (p,d) column, all 32 neighbors in regs
        int w = t >> 5, lane = t & 31;
        for (int pass = 0; pass < 2; pass++) {
            int pl = (pass << 1) + (w >> 2);         // local group 0..3
            int d  = ((w & 3) << 5) + lane;          // channel 0..127
            const float* hbase = &H3[(pl << 5) * 132];
            float acc[32];
#pragma unroll
            for (int r = 0; r < 32; r++) acc[r] = 0.f;
            for (int k4 = 0; k4 < 32; k4++) {
                int kb = 3 + (k4 << 2);
                float a0 = aSm[(kb + 0) * 128 + d];
                float a1 = aSm[(kb + 1) * 128 + d];
                float a2 = aSm[(kb + 2) * 128 + d];
                float a3v = aSm[(kb + 3) * 128 + d];
#pragma unroll
                for (int r = 0; r < 32; r++) {
                    float4 h = *(const float4*)&hbase[r * 132 + (k4 << 2)];
                    acc[r] += h.x * a0 + h.y * a1 + h.z * a2 + h.w * a3v;
                }
            }
            float av0 = aSm[d], av1 = aSm[128 + d], av2 = aSm[256 + d];
            float nx0 = nX[pl * 4 + 0], nx1 = nX[pl * 4 + 1], nx2 = nX[pl * 4 + 2];
            float Fpd = Fp[(pl << 7) + d];
            float mx = -1e30f;
#pragma unroll
            for (int r = 0; r < 32; r++) {
                int row = (pl << 5) + r;
                float ev = Fpd - acc[r]
                    + (nx0 - relx[row * 3 + 0]) * av0
                    + (nx1 - relx[row * 3 + 1]) * av1
                    + (nx2 - relx[row * 3 + 2]) * av2;
                ev = ev > 0.f ? ev : ALPHA * ev;      // leaky relu
                acc[r] = ev;
                mx = fmaxf(mx, ev);
            }
            float ssum = 0.f;
#pragma unroll
            for (int r = 0; r < 32; r++) {
                float ee = __expf(acc[r] - mx);
                acc[r] = ee;
                ssum += ee;
            }
            float pooled = 0.f;
#pragma unroll
            for (int r = 0; r < 32; r++)
                pooled += acc[r] * hbase[r * 132 + d];
            out[OUT2_OFF + (b * 128 + d) * P + p0 + pl] = pooled / ssum;
        }
    }
}

// ---------------------------------------------------------------------------
extern "C" void kernel_launch(void* const* d_in, const int* in_sizes, int n_in,
                              void* d_out, int out_size) {
    const float* xyz    = (const float*)d_in[0];
    const float* pts    = (const float*)d_in[1];
    const int*   fpsIdx = (const int*)d_in[2];
    const int*   grpIdx = (const int*)d_in[3];
    const float* w1 = (const float*)d_in[4];
    const float* b1 = (const float*)d_in[5];
    const float* g1 = (const float*)d_in[6];
    const float* bt1 = (const float*)d_in[7];
    const float* m1 = (const float*)d_in[8];
    const float* v1 = (const float*)d_in[9];
    const float* w2 = (const float*)d_in[10];
    const float* b2 = (const float*)d_in[11];
    const float* g2 = (const float*)d_in[12];
    const float* bt2 = (const float*)d_in[13];
    const float* m2 = (const float*)d_in[14];
    const float* v2 = (const float*)d_in[15];
    const float* w3 = (const float*)d_in[16];
    const float* b3 = (const float*)d_in[17];
    const float* g3 = (const float*)d_in[18];
    const float* bt3 = (const float*)d_in[19];
    const float* m3 = (const float*)d_in[20];
    const float* v3 = (const float*)d_in[21];
    const float* aG = (const float*)d_in[22];
    float* out = (float*)d_out;

    transpose_kernel<<<1024, 256>>>(xyz, pts);

    const int smBytes = 54084 * 4;   // 216336 B
    cudaFuncSetAttribute(main_kernel,
                         cudaFuncAttributeMaxDynamicSharedMemorySize, smBytes);
    int smCount = 148;
    cudaDeviceGetAttribute(&smCount, cudaDevAttrMultiProcessorCount, 0);

    main_kernel<<<smCount, 256, smBytes>>>(
        fpsIdx, grpIdx,
        w1, b1, g1, bt1, m1, v1,
        w2, b2, g2, bt2, m2, v2,
        w3, b3, g3, bt3, m3, v3,
        aG, out);
}

// round 4
// speedup vs baseline: 1.0804x; 1.0804x over previous
#include <cuda_runtime.h>

#define EPSBN 1e-5f
#define ALPHA 0.2f

typedef unsigned long long ull;

static constexpr int B = 16, N = 4096, P = 1024, S = 32;
static constexpr int NTILES = (B * P) / 4;   // 4096 tiles, 4 groups each
static constexpr int OUT2_OFF = B * 3 * P;   // 49152

// fused transposed features: [b][n][0..2]=xyz, [3..66]=points, [67]=0
__device__ __align__(16) float g_xpt[(size_t)B * N * 68];

// ---------------------------------------------------------------------------
// packed f32x2 helpers
// ---------------------------------------------------------------------------
__device__ __forceinline__ void ffma2(ull& d, ull a, ull b) {
    asm("fma.rn.f32x2 %0, %1, %2, %0;" : "+l"(d) : "l"(a), "l"(b));
}
__device__ __forceinline__ ull pack2(float lo, float hi) {
    ull r; asm("mov.b64 %0, {%1, %2};" : "=l"(r) : "f"(lo), "f"(hi)); return r;
}
__device__ __forceinline__ float hsum2(ull v) {
    float lo, hi;
    asm("mov.b64 {%0, %1}, %2;" : "=f"(lo), "=f"(hi) : "l"(v));
    return lo + hi;
}

// ---------------------------------------------------------------------------
// Kernel 1: transpose (B,3,N)+(B,64,N) channel-major -> (B,N,68) row-major
// ---------------------------------------------------------------------------
__global__ void __launch_bounds__(256) transpose_kernel(
    const float* __restrict__ xyz, const float* __restrict__ pts)
{
    __shared__ float sm[67 * 65];
    int b  = blockIdx.x >> 6;
    int n0 = (blockIdx.x & 63) << 6;
    int t  = threadIdx.x;
    for (int idx = t; idx < 67 * 64; idx += 256) {
        int c = idx >> 6, i = idx & 63;
        float v = (c < 3) ? xyz[(b * 3 + c) * N + n0 + i]
                          : pts[(b * 64 + (c - 3)) * N + n0 + i];
        sm[c * 65 + i] = v;
    }
    __syncthreads();
    for (int idx = t; idx < 64 * 17; idx += 256) {
        int row = idx / 17, c4 = idx % 17;
        int cb = c4 << 2;
        float4 v;
        v.x = sm[(cb + 0) * 65 + row];
        v.y = sm[(cb + 1) * 65 + row];
        v.z = sm[(cb + 2) * 65 + row];
        v.w = (cb + 3 < 67) ? sm[(cb + 3) * 65 + row] : 0.f;
        *(float4*)&g_xpt[((size_t)(b * N + n0 + row)) * 68 + cb] = v;
    }
}

// ---------------------------------------------------------------------------
// Shared-memory GEMM (f32x2 packed over K):
// out[r][d] = relu(sum_k in[r][k]*W[d][k] + bias[d])
// in: 132 rows, stride 68.  W: rows = output channels, stride 68.
// Thread tiling: 4 rows x 8 cols per thread (cols strided by 8).
// ---------------------------------------------------------------------------
__device__ __forceinline__ void gemm_relu2(
    const float* __restrict__ sIn, const float* __restrict__ sW,
    const float* __restrict__ sBias, float* __restrict__ sOut,
    int outStride, int K4, int dOff, int t)
{
    int d_blk = t & 7;
    int rb0   = t >> 3;
    for (int rb = rb0; rb < 33; rb += 32) {
        int r0 = rb << 2;
        ull acc[4][8];
#pragma unroll
        for (int i = 0; i < 4; i++)
#pragma unroll
            for (int j = 0; j < 8; j++) acc[i][j] = 0ull;
        for (int k4 = 0; k4 < K4; k4++) {
            ulonglong2 xv[4];
#pragma unroll
            for (int i = 0; i < 4; i++)
                xv[i] = *(const ulonglong2*)&sIn[(r0 + i) * 68 + (k4 << 2)];
#pragma unroll
            for (int j = 0; j < 8; j++) {
                ulonglong2 wv = *(const ulonglong2*)&sW[(dOff + d_blk + (j << 3)) * 68 + (k4 << 2)];
#pragma unroll
                for (int i = 0; i < 4; i++) {
                    ffma2(acc[i][j], xv[i].x, wv.x);
                    ffma2(acc[i][j], xv[i].y, wv.y);
                }
            }
        }
#pragma unroll
        for (int j = 0; j < 8; j++) {
            int d = dOff + d_blk + (j << 3);
            float bb = sBias[d];
#pragma unroll
            for (int i = 0; i < 4; i++) {
                float v = hsum2(acc[i][j]) + bb;
                sOut[(r0 + i) * outStride + d] = v > 0.f ? v : 0.f;
            }
        }
    }
}

// ---------------------------------------------------------------------------
// Main fused kernel: persistent CTAs, each tile = 4 groups (132 rows)
// smem layout (floats):
//  W1s 0(4352) W2s 4352(4352) W3s 8704(8704) c1 17408(64) c2 17472(64)
//  c3 17536(128) X 17664(8976) H1 26640(8976) H3 35616(17424)
//  relx 53040(384) nX 53424(16) rowGi 53440(132) -> 53572 floats
// 'a' (131x128 = 16768 fl) overlays X+H1 during the attention phase.
// ---------------------------------------------------------------------------
__global__ void __launch_bounds__(256, 1) main_kernel(
    const int* __restrict__ fpsIdx, const int* __restrict__ grpIdx,
    const float* __restrict__ w1, const float* __restrict__ b1,
    const float* __restrict__ g1, const float* __restrict__ bt1,
    const float* __restrict__ m1, const float* __restrict__ v1,
    const float* __restrict__ w2, const float* __restrict__ b2,
    const float* __restrict__ g2, const float* __restrict__ bt2,
    const float* __restrict__ m2, const float* __restrict__ v2,
    const float* __restrict__ w3, const float* __restrict__ b3,
    const float* __restrict__ g3, const float* __restrict__ bt3,
    const float* __restrict__ m3, const float* __restrict__ v3,
    const float* __restrict__ aG,
    float* __restrict__ out)
{
    extern __shared__ float sm[];
    float* W1s  = sm;
    float* W2s  = sm + 4352;
    float* W3s  = sm + 8704;
    float* c1s  = sm + 17408;
    float* c2s  = sm + 17472;
    float* c3s  = sm + 17536;
    float* X    = sm + 17664;   // also aSm during attention
    float* H1   = sm + 26640;
    float* H3   = sm + 35616;
    float* relx = sm + 53040;
    float* nX   = sm + 53424;
    int*  rowGi = (int*)(sm + 53440);
    float* aSm  = X;

    int t = threadIdx.x;

    // fold BN into weights (once per CTA)
    for (int idx = t; idx < 64 * 68; idx += 256) {
        int d = idx / 68, k = idx % 68;
        float s1 = g1[d] * rsqrtf(v1[d] + EPSBN);
        float s2 = g2[d] * rsqrtf(v2[d] + EPSBN);
        W1s[idx] = (k < 67) ? w1[d * 67 + k] * s1 : 0.f;
        W2s[idx] = (k < 64) ? w2[d * 64 + k] * s2 : 0.f;
    }
    for (int idx = t; idx < 128 * 68; idx += 256) {
        int d = idx / 68, k = idx % 68;
        float s3 = g3[d] * rsqrtf(v3[d] + EPSBN);
        W3s[idx] = (k < 64) ? w3[d * 64 + k] * s3 : 0.f;
    }
    if (t < 64) {
        float s1 = g1[t] * rsqrtf(v1[t] + EPSBN);
        float s2 = g2[t] * rsqrtf(v2[t] + EPSBN);
        c1s[t] = (b1[t] - m1[t]) * s1 + bt1[t];
        c2s[t] = (b2[t] - m2[t]) * s2 + bt2[t];
    }
    if (t < 128) {
        float s3 = g3[t] * rsqrtf(v3[t] + EPSBN);
        c3s[t] = (b3[t] - m3[t]) * s3 + bt3[t];
    }

    for (int tile = blockIdx.x; tile < NTILES; tile += gridDim.x) {
        __syncthreads();                       // protect smem from prev tile
        int b  = tile >> 8;
        int p0 = (tile & 255) << 2;

        if (t < 132) {
            int gi;
            if (t < 128) gi = grpIdx[((b * P + p0 + (t >> 5)) << 5) + (t & 31)];
            else         gi = fpsIdx[b * P + p0 + (t - 128)];
            rowGi[t] = gi;
        }
        __syncthreads();
        if (t < 12) {
            int p = t / 3, c = t % 3;
            float v = g_xpt[((size_t)(b * N + rowGi[128 + p])) * 68 + c];
            nX[p * 4 + c] = v;
            out[(b * 3 + c) * P + p0 + p] = v;   // new_xyz output (B,3,P)
        }
        __syncthreads();

        // gather 132 feature rows (67 valid floats each)
        for (int idx = t; idx < 132 * 17; idx += 256) {
            int row = idx / 17, c4 = idx % 17;
            float4 v = *(const float4*)&g_xpt[((size_t)(b * N + rowGi[row])) * 68 + (c4 << 2)];
            if (c4 == 0 && row < 128) {          // relative xyz for neighbor rows
                int p = row >> 5;
                v.x -= nX[p * 4 + 0];
                v.y -= nX[p * 4 + 1];
                v.z -= nX[p * 4 + 2];
                relx[row * 3 + 0] = v.x;
                relx[row * 3 + 1] = v.y;
                relx[row * 3 + 2] = v.z;
            }
            *(float4*)&X[row * 68 + (c4 << 2)] = v;
        }
        __syncthreads();

        gemm_relu2(X,  W1s, c1s, H1, 68,  17, 0,  t);   // 67 -> 64
        __syncthreads();
        gemm_relu2(H1, W2s, c2s, X,  68,  16, 0,  t);   // 64 -> 64 (H2 in X)
        __syncthreads();
        gemm_relu2(X,  W3s, c3s, H3, 132, 16, 0,  t);   // 64 -> 128
        gemm_relu2(X,  W3s, c3s, H3, 132, 16, 64, t);
        __syncthreads();

        // load attention matrix a into freed X+H1 region
        for (int idx = t; idx < (131 * 128) / 4; idx += 256)
            *(float4*)&aSm[idx << 2] = *(const float4*)&aG[idx << 2];
        __syncthreads();

        // attention: thread owns one (p,d) column; acc[0..31] = neighbor
        // H3 . a3  (f32x2 packed over k), acc[32] = fps row (== Fp term)
        int w = t >> 5, lane = t & 31;
        for (int pass = 0; pass < 2; pass++) {
            int pl = (pass << 1) + (w >> 2);         // local group 0..3
            int d  = ((w & 3) << 5) + lane;          // channel 0..127
            const float* hbase = &H3[(pl << 5) * 132];
            const float* hfps  = &H3[(128 + pl) * 132];
            ull acc[33];
#pragma unroll
            for (int r = 0; r < 33; r++) acc[r] = 0ull;
            for (int k4 = 0; k4 < 32; k4++) {
                int kb = 3 + (k4 << 2);
                float a0  = aSm[(kb + 0) * 128 + d];
                float a1  = aSm[(kb + 1) * 128 + d];
                float a2  = aSm[(kb + 2) * 128 + d];
                float a3v = aSm[(kb + 3) * 128 + d];
                ull ap0 = pack2(a0, a1);
                ull ap1 = pack2(a2, a3v);
#pragma unroll
                for (int r = 0; r < 32; r++) {
                    ulonglong2 h = *(const ulonglong2*)&hbase[r * 132 + (k4 << 2)];
                    ffma2(acc[r], h.x, ap0);
                    ffma2(acc[r], h.y, ap1);
                }
                ulonglong2 hf = *(const ulonglong2*)&hfps[k4 << 2];
                ffma2(acc[32], hf.x, ap0);
                ffma2(acc[32], hf.y, ap1);
            }
            float Fpd = hsum2(acc[32]);
            float av0 = aSm[d], av1 = aSm[128 + d], av2 = aSm[256 + d];
            float nx0 = nX[pl * 4 + 0], nx1 = nX[pl * 4 + 1], nx2 = nX[pl * 4 + 2];
            float ev_arr[32];
            float mx = -1e30f;
#pragma unroll
            for (int r = 0; r < 32; r++) {
                int row = (pl << 5) + r;
                float ev = Fpd - hsum2(acc[r])
                    + (nx0 - relx[row * 3 + 0]) * av0
                    + (nx1 - relx[row * 3 + 1]) * av1
                    + (nx2 - relx[row * 3 + 2]) * av2;
                ev = ev > 0.f ? ev : ALPHA * ev;      // leaky relu
                ev_arr[r] = ev;
                mx = fmaxf(mx, ev);
            }
            float ssum = 0.f;
#pragma unroll
            for (int r = 0; r < 32; r++) {
                float ee = __expf(ev_arr[r] - mx);
                ev_arr[r] = ee;
                ssum += ee;
            }
            float pooled = 0.f;
#pragma unroll
            for (int r = 0; r < 32; r++)
                pooled += ev_arr[r] * hbase[r * 132 + d];
            out[OUT2_OFF + (b * 128 + d) * P + p0 + pl] = pooled / ssum;
        }
    }
}

// ---------------------------------------------------------------------------
extern "C" void kernel_launch(void* const* d_in, const int* in_sizes, int n_in,
                              void* d_out, int out_size) {
    const float* xyz    = (const float*)d_in[0];
    const float* pts    = (const float*)d_in[1];
    const int*   fpsIdx = (const int*)d_in[2];
    const int*   grpIdx = (const int*)d_in[3];
    const float* w1 = (const float*)d_in[4];
    const float* b1 = (const float*)d_in[5];
    const float* g1 = (const float*)d_in[6];
    const float* bt1 = (const float*)d_in[7];
    const float* m1 = (const float*)d_in[8];
    const float* v1 = (const float*)d_in[9];
    const float* w2 = (const float*)d_in[10];
    const float* b2 = (const float*)d_in[11];
    const float* g2 = (const float*)d_in[12];
    const float* bt2 = (const float*)d_in[13];
    const float* m2 = (const float*)d_in[14];
    const float* v2 = (const float*)d_in[15];
    const float* w3 = (const float*)d_in[16];
    const float* b3 = (const float*)d_in[17];
    const float* g3 = (const float*)d_in[18];
    const float* bt3 = (const float*)d_in[19];
    const float* m3 = (const float*)d_in[20];
    const float* v3 = (const float*)d_in[21];
    const float* aG = (const float*)d_in[22];
    float* out = (float*)d_out;

    transpose_kernel<<<1024, 256>>>(xyz, pts);

    const int smBytes = 53572 * 4;   // 214288 B
    cudaFuncSetAttribute(main_kernel,
                         cudaFuncAttributeMaxDynamicSharedMemorySize, smBytes);
    int smCount = 148;
    cudaDeviceGetAttribute(&smCount, cudaDevAttrMultiProcessorCount, 0);

    main_kernel<<<smCount, 256, smBytes>>>(
        fpsIdx, grpIdx,
        w1, b1, g1, bt1, m1, v1,
        w2, b2, g2, bt2, m2, v2,
        w3, b3, g3, bt3, m3, v3,
        aG, out);
}